// round 1
// baseline (speedup 1.0000x reference)
#include <cuda_runtime.h>
#include <math.h>

// Problem constants (fixed by reference_code)
#define B_    4
#define S_    2048
#define H_    768
#define NSEG  256
#define NROWS 2048      // B * S/4  (query rows)
#define QPB   512       // S/4 query rows per batch
#define HALF  1024      // S/2 mask boundary

// -------- scratch (no allocations allowed) --------
__device__ float g_segsum [B_ * NSEG * H_];    // 3 MB
__device__ float g_segproj[B_ * NSEG * H_];    // 3 MB
__device__ float g_sdot   [B_ * NSEG * NSEG];  // 1 MB
__device__ int   g_cnt    [B_ * NSEG];         // unmasked count per segment
__device__ int   g_first  [B_ * NSEG];         // first unmasked j per segment
__device__ float g_loss   [NROWS];
__device__ int   g_corr   [NROWS];

// ---------------------------------------------------------------------------
// K1: segmented sum over sorted indicator + unmasked counts / first-index
// grid (NSEG, B), block 256
// ---------------------------------------------------------------------------
__global__ __launch_bounds__(256) void k_segsum(const float* __restrict__ x,
                                                const int* __restrict__ ind) {
    const int v = blockIdx.x;
    const int b = blockIdx.y;
    const int* row = ind + b * S_;

    // lower_bound(v)
    int lo;
    { int l = 0, r = S_;
      while (l < r) { int m = (l + r) >> 1; if (row[m] < v) l = m + 1; else r = m; }
      lo = l; }
    // upper_bound(v)
    int hi;
    { int l = lo, r = S_;
      while (l < r) { int m = (l + r) >> 1; if (row[m] <= v) l = m + 1; else r = m; }
      hi = l; }

    float* out = g_segsum + ((size_t)b * NSEG + v) * H_;
    for (int h = threadIdx.x; h < H_; h += blockDim.x) {
        float acc = 0.0f;
        const float* xp = x + ((size_t)b * S_ + lo) * H_ + h;
        for (int i = lo; i < hi; i++) { acc += *xp; xp += H_; }
        out[h] = acc;
    }
    if (threadIdx.x == 0) {
        int lo2 = lo > HALF ? lo : HALF;
        int c   = hi - lo2; if (c < 0) c = 0;
        g_cnt  [b * NSEG + v] = c;
        g_first[b * NSEG + v] = lo2;
    }
}

// ---------------------------------------------------------------------------
// K2: segproj = tanh(segsum @ W^T + bias)    (M=1024, N=768, K=768, fp32)
// 64x64 tile, BK=16, 256 threads, 4x4 micro-tile
// grid (N/64, M/64)
// ---------------------------------------------------------------------------
__global__ __launch_bounds__(256) void k_proj(const float* __restrict__ W,
                                              const float* __restrict__ bias) {
    __shared__ float As[16][64];
    __shared__ float Bs[16][64];
    const float* A = g_segsum;
    float*       C = g_segproj;
    const int K = H_, N = H_;

    const int tid = threadIdx.x;
    const int tx = tid & 15, ty = tid >> 4;
    const int bm = blockIdx.y * 64, bn = blockIdx.x * 64;
    const int lm = tid >> 2;            // 0..63
    const int lk = (tid & 3) << 2;      // 0,4,8,12

    float acc[4][4] = {};

    for (int k0 = 0; k0 < K; k0 += 16) {
        float4 a = *(const float4*)(A + (size_t)(bm + lm) * K + k0 + lk);
        float4 w = *(const float4*)(W + (size_t)(bn + lm) * K + k0 + lk);
        As[lk + 0][lm] = a.x; As[lk + 1][lm] = a.y; As[lk + 2][lm] = a.z; As[lk + 3][lm] = a.w;
        Bs[lk + 0][lm] = w.x; Bs[lk + 1][lm] = w.y; Bs[lk + 2][lm] = w.z; Bs[lk + 3][lm] = w.w;
        __syncthreads();
        #pragma unroll
        for (int kk = 0; kk < 16; kk++) {
            float4 ra = *(const float4*)&As[kk][ty << 2];
            float4 rb = *(const float4*)&Bs[kk][tx << 2];
            float av[4] = {ra.x, ra.y, ra.z, ra.w};
            float bv[4] = {rb.x, rb.y, rb.z, rb.w};
            #pragma unroll
            for (int i = 0; i < 4; i++)
                #pragma unroll
                for (int j = 0; j < 4; j++)
                    acc[i][j] += av[i] * bv[j];
        }
        __syncthreads();
    }

    const int n0 = bn + (tx << 2);
    float b0 = bias[n0 + 0], b1 = bias[n0 + 1], b2 = bias[n0 + 2], b3 = bias[n0 + 3];
    #pragma unroll
    for (int i = 0; i < 4; i++) {
        int m = bm + (ty << 2) + i;
        float4 o;
        o.x = tanhf(acc[i][0] + b0);
        o.y = tanhf(acc[i][1] + b1);
        o.z = tanhf(acc[i][2] + b2);
        o.w = tanhf(acc[i][3] + b3);
        *(float4*)(C + (size_t)m * N + n0) = o;
    }
}

// ---------------------------------------------------------------------------
// K3: Sdot[b] = P[b] @ P[b]^T   (M=N=256, K=768 per batch)
// grid (4, 4, B)
// ---------------------------------------------------------------------------
__global__ __launch_bounds__(256) void k_sdot() {
    __shared__ float As[16][64];
    __shared__ float Bs[16][64];
    const int b = blockIdx.z;
    const float* P = g_segproj + (size_t)b * NSEG * H_;
    float*       C = g_sdot    + (size_t)b * NSEG * NSEG;
    const int K = H_, N = NSEG;

    const int tid = threadIdx.x;
    const int tx = tid & 15, ty = tid >> 4;
    const int bm = blockIdx.y * 64, bn = blockIdx.x * 64;
    const int lm = tid >> 2;
    const int lk = (tid & 3) << 2;

    float acc[4][4] = {};

    for (int k0 = 0; k0 < K; k0 += 16) {
        float4 a = *(const float4*)(P + (size_t)(bm + lm) * K + k0 + lk);
        float4 w = *(const float4*)(P + (size_t)(bn + lm) * K + k0 + lk);
        As[lk + 0][lm] = a.x; As[lk + 1][lm] = a.y; As[lk + 2][lm] = a.z; As[lk + 3][lm] = a.w;
        Bs[lk + 0][lm] = w.x; Bs[lk + 1][lm] = w.y; Bs[lk + 2][lm] = w.z; Bs[lk + 3][lm] = w.w;
        __syncthreads();
        #pragma unroll
        for (int kk = 0; kk < 16; kk++) {
            float4 ra = *(const float4*)&As[kk][ty << 2];
            float4 rb = *(const float4*)&Bs[kk][tx << 2];
            float av[4] = {ra.x, ra.y, ra.z, ra.w};
            float bv[4] = {rb.x, rb.y, rb.z, rb.w};
            #pragma unroll
            for (int i = 0; i < 4; i++)
                #pragma unroll
                for (int j = 0; j < 4; j++)
                    acc[i][j] += av[i] * bv[j];
        }
        __syncthreads();
    }

    const int n0 = bn + (tx << 2);
    #pragma unroll
    for (int i = 0; i < 4; i++) {
        int m = bm + (ty << 2) + i;
        float4 o;
        o.x = acc[i][0]; o.y = acc[i][1]; o.z = acc[i][2]; o.w = acc[i][3];
        *(float4*)(C + (size_t)m * N + n0) = o;
    }
}

// ---------------------------------------------------------------------------
// K4: per query row: masked logsumexp + argmax over 256 segments
// one warp per row; 2048 rows
// ---------------------------------------------------------------------------
__global__ __launch_bounds__(256) void k_rows(const int* __restrict__ ind,
                                              const int* __restrict__ clc) {
    const int warp = (blockIdx.x * blockDim.x + threadIdx.x) >> 5;
    const int lane = threadIdx.x & 31;
    if (warp >= NROWS) return;
    const int b = warp >> 9;         // / 512
    const int i = warp & (QPB - 1);  // % 512
    const int q     = ind[b * S_ + i];
    const int label = clc[b * S_ + i];   // in [1, S)

    const float* srow = g_sdot + ((size_t)b * NSEG + q) * NSEG;
    const int*   cnt  = g_cnt  + b * NSEG;
    const int*   fst  = g_first + b * NSEG;

    float s[8]; int c[8];
    #pragma unroll
    for (int t = 0; t < 8; t++) {
        int v = lane + 32 * t;
        s[t] = srow[v];
        c[t] = cnt[v];
    }

    // max over unmasked segments, tie-break by smallest first-j
    float bmax = -INFINITY; int bj = 0x7fffffff;
    #pragma unroll
    for (int t = 0; t < 8; t++) {
        if (c[t] > 0) {
            int j = fst[lane + 32 * t];
            if (s[t] > bmax || (s[t] == bmax && j < bj)) { bmax = s[t]; bj = j; }
        }
    }
    #pragma unroll
    for (int off = 16; off; off >>= 1) {
        float os = __shfl_xor_sync(0xffffffffu, bmax, off);
        int   oj = __shfl_xor_sync(0xffffffffu, bj,   off);
        if (os > bmax || (os == bmax && oj < bj)) { bmax = os; bj = oj; }
    }

    // Z = sum_v cnt[v] * exp(s - max)   (masked entries are exactly 0 in fp32)
    float z = 0.0f;
    #pragma unroll
    for (int t = 0; t < 8; t++)
        if (c[t] > 0) z += (float)c[t] * expf(s[t] - bmax);
    #pragma unroll
    for (int off = 16; off; off >>= 1)
        z += __shfl_xor_sync(0xffffffffu, z, off);

    if (lane == 0) {
        int vlab = ind[b * S_ + label];
        float slab = srow[vlab];
        float loss = (logf(z) + bmax) - slab;
        if (label < HALF) loss += 1.0e9f;   // masked label: logit was s - 1e9
        g_loss[warp] = loss;
        g_corr[warp] = (bj == label) ? 1 : 0;
    }
}

// ---------------------------------------------------------------------------
// K5: final reduction -> 6 scalars
// sep = even positional index (= even row index r = b*512+i), tok = odd
// ---------------------------------------------------------------------------
__global__ __launch_bounds__(256) void k_final(float* __restrict__ out) {
    __shared__ double sls[256], slt[256];
    __shared__ int    scs[256], sct[256];
    const int t = threadIdx.x;
    double ls = 0.0, lt = 0.0;
    int cs = 0, ct = 0;
    for (int r = t; r < NROWS; r += 256) {
        if (r & 1) { lt += (double)g_loss[r]; ct += g_corr[r]; }
        else       { ls += (double)g_loss[r]; cs += g_corr[r]; }
    }
    sls[t] = ls; slt[t] = lt; scs[t] = cs; sct[t] = ct;
    __syncthreads();
    for (int off = 128; off; off >>= 1) {
        if (t < off) {
            sls[t] += sls[t + off]; slt[t] += slt[t + off];
            scs[t] += scs[t + off]; sct[t] += sct[t + off];
        }
        __syncthreads();
    }
    if (t == 0) {
        const double n = (double)(NROWS / 2);       // 1024
        out[0] = (float)(sls[0] / n);               // sep_loss
        out[1] = (float)scs[0];                     // sep_correct
        out[2] = (float)(n + 1e-6);                 // sep_count -> 1024.0f
        out[3] = (float)(slt[0] / n);               // tok_loss
        out[4] = (float)sct[0];                     // tok_correct
        out[5] = (float)(n + 1e-6);                 // tok_count
    }
}

// ---------------------------------------------------------------------------
extern "C" void kernel_launch(void* const* d_in, const int* in_sizes, int n_in,
                              void* d_out, int out_size) {
    const float* x    = (const float*)d_in[0];   // encoded_states (B,S,H)
    const float* W    = (const float*)d_in[1];   // (H,H)
    const float* bias = (const float*)d_in[2];   // (H,)
    const int*   ind  = (const int*)  d_in[3];   // indicator (B,S)
    const int*   clc  = (const int*)  d_in[4];   // clc_label (B,S)
    float* out = (float*)d_out;

    (void)in_sizes; (void)n_in; (void)out_size;

    dim3 g1(NSEG, B_);
    k_segsum<<<g1, 256>>>(x, ind);

    dim3 g2(H_ / 64, (B_ * NSEG) / 64);          // (12, 16)
    k_proj<<<g2, 256>>>(W, bias);

    dim3 g3(NSEG / 64, NSEG / 64, B_);           // (4, 4, 4)
    k_sdot<<<g3, 256>>>();

    k_rows<<<(NROWS * 32) / 256, 256>>>(ind, clc);

    k_final<<<1, 256>>>(out);
}